// round 1
// baseline (speedup 1.0000x reference)
#include <cuda_runtime.h>
#include <cuda_bf16.h>

// Problem dims (fixed)
#define Dm   256
#define Bsz  4
#define Sq   512
#define HWk  4096
#define NH   8
#define HD   32

// Scratch (no cudaMalloc allowed)
__device__ float g_Q[Bsz * Sq * Dm];      // (B,S,D) projected Q
__device__ float g_K[Bsz * HWk * Dm];     // (B,HW,D)
__device__ float g_V[Bsz * HWk * Dm];     // (B,HW,D)
__device__ float g_A[Bsz * Sq * Dm];      // attention output (B,S,D)

// ---------------------------------------------------------------------------
// GEMM: C[m,n] = sum_k A[m,k] * W[n,k] + bias[n]
// A row-major (M x 256), W row-major (256 x 256). BM=BN=64, BK=16, 256 thr.
// ---------------------------------------------------------------------------
__global__ __launch_bounds__(256)
void gemm_nt_bias(const float* __restrict__ A, const float* __restrict__ W,
                  const float* __restrict__ bias, float* __restrict__ C)
{
    __shared__ float As[16][64];
    __shared__ float Ws[16][64];

    const int bm = blockIdx.y * 64;
    const int bn = blockIdx.x * 64;
    const int tid = threadIdx.x;

    const int tr = (tid >> 4) << 2;   // 0..60 step 4
    const int tc = (tid & 15) << 2;   // 0..60 step 4

    const int lr = tid >> 2;          // 0..63
    const int lc = (tid & 3) << 2;    // 0,4,8,12

    float acc[4][4];
#pragma unroll
    for (int i = 0; i < 4; i++)
#pragma unroll
        for (int j = 0; j < 4; j++) acc[i][j] = 0.f;

    for (int k0 = 0; k0 < Dm; k0 += 16) {
        float4 av = *(const float4*)(A + (size_t)(bm + lr) * Dm + k0 + lc);
        As[lc + 0][lr] = av.x; As[lc + 1][lr] = av.y;
        As[lc + 2][lr] = av.z; As[lc + 3][lr] = av.w;
        float4 wv = *(const float4*)(W + (size_t)(bn + lr) * Dm + k0 + lc);
        Ws[lc + 0][lr] = wv.x; Ws[lc + 1][lr] = wv.y;
        Ws[lc + 2][lr] = wv.z; Ws[lc + 3][lr] = wv.w;
        __syncthreads();

#pragma unroll
        for (int k = 0; k < 16; k++) {
            float4 a4 = *(const float4*)&As[k][tr];
            float4 b4 = *(const float4*)&Ws[k][tc];
            float a[4] = {a4.x, a4.y, a4.z, a4.w};
            float b[4] = {b4.x, b4.y, b4.z, b4.w};
#pragma unroll
            for (int i = 0; i < 4; i++)
#pragma unroll
                for (int j = 0; j < 4; j++)
                    acc[i][j] += a[i] * b[j];
        }
        __syncthreads();
    }

#pragma unroll
    for (int i = 0; i < 4; i++) {
#pragma unroll
        for (int j = 0; j < 4; j++) {
            C[(size_t)(bm + tr + i) * Dm + bn + tc + j] = acc[i][j] + bias[bn + tc + j];
        }
    }
}

// ---------------------------------------------------------------------------
// KV projection GEMM: input key_value is (B, D, HW) i.e. A^T layout:
// A[m,k] = kv[b, k, m]. C (B, HW, D): C[b,m,n] = sum_k kv[b,k,m]*W[n,k]+bias[n]
// ---------------------------------------------------------------------------
__global__ __launch_bounds__(256)
void gemm_kv_bias(const float* __restrict__ KVin, const float* __restrict__ W,
                  const float* __restrict__ bias, float* __restrict__ C)
{
    const int b = blockIdx.z;
    const float* A = KVin + (size_t)b * Dm * HWk;  // A[k*HW + m]
    float* Cb = C + (size_t)b * HWk * Dm;

    __shared__ float As[16][64];
    __shared__ float Ws[16][64];

    const int bm = blockIdx.y * 64;
    const int bn = blockIdx.x * 64;
    const int tid = threadIdx.x;

    const int tr = (tid >> 4) << 2;
    const int tc = (tid & 15) << 2;

    // A tile load: k-row major, m contiguous (coalesced along hw)
    const int kr = tid >> 4;          // 0..15
    const int m4 = (tid & 15) << 2;   // 0..60
    // W tile load mapping (same as gemm_nt_bias)
    const int lr = tid >> 2;
    const int lc = (tid & 3) << 2;

    float acc[4][4];
#pragma unroll
    for (int i = 0; i < 4; i++)
#pragma unroll
        for (int j = 0; j < 4; j++) acc[i][j] = 0.f;

    for (int k0 = 0; k0 < Dm; k0 += 16) {
        float4 av = *(const float4*)(A + (size_t)(k0 + kr) * HWk + bm + m4);
        *(float4*)&As[kr][m4] = av;
        float4 wv = *(const float4*)(W + (size_t)(bn + lr) * Dm + k0 + lc);
        Ws[lc + 0][lr] = wv.x; Ws[lc + 1][lr] = wv.y;
        Ws[lc + 2][lr] = wv.z; Ws[lc + 3][lr] = wv.w;
        __syncthreads();

#pragma unroll
        for (int k = 0; k < 16; k++) {
            float4 a4 = *(const float4*)&As[k][tr];
            float4 b4 = *(const float4*)&Ws[k][tc];
            float a[4] = {a4.x, a4.y, a4.z, a4.w};
            float bb[4] = {b4.x, b4.y, b4.z, b4.w};
#pragma unroll
            for (int i = 0; i < 4; i++)
#pragma unroll
                for (int j = 0; j < 4; j++)
                    acc[i][j] += a[i] * bb[j];
        }
        __syncthreads();
    }

#pragma unroll
    for (int i = 0; i < 4; i++) {
#pragma unroll
        for (int j = 0; j < 4; j++) {
            Cb[(size_t)(bm + tr + i) * Dm + bn + tc + j] = acc[i][j] + bias[bn + tc + j];
        }
    }
}

// ---------------------------------------------------------------------------
// Flash attention: per CTA = 64 queries of one (b, head).
// 256 threads, 4 threads per query row. q row (scaled) in registers.
// K/V tiles of 64 keys in SMEM (row stride 36 floats -> conflict-free LDS.128
// with the interleaved key partition c = cc*4 + p).
// ---------------------------------------------------------------------------
#define HD_PAD 36

__global__ __launch_bounds__(256)
void attn_kernel(const float* __restrict__ Q, const float* __restrict__ K,
                 const float* __restrict__ V, float* __restrict__ O)
{
    const int h  = blockIdx.y;
    const int b  = blockIdx.z;
    const int q0 = blockIdx.x * 64;

    __shared__ float Ks[64][HD_PAD];
    __shared__ float Vs[64][HD_PAD];

    const int tid = threadIdx.x;
    const int r = tid >> 2;     // query row 0..63
    const int p = tid & 3;      // partition 0..3

    const float scale = 0.17677669529663687f;  // 1/sqrt(32)

    // q row into registers (pre-scaled)
    float q[HD];
    {
        const float* qptr = Q + ((size_t)(b * Sq + q0 + r)) * Dm + h * HD;
#pragma unroll
        for (int d = 0; d < HD; d += 4) {
            float4 v = *(const float4*)(qptr + d);
            q[d + 0] = v.x * scale; q[d + 1] = v.y * scale;
            q[d + 2] = v.z * scale; q[d + 3] = v.w * scale;
        }
    }

    float m_i = -1e30f;
    float l_i = 0.f;        // per-thread partial (over this thread's keys)
    float o[HD];
#pragma unroll
    for (int d = 0; d < HD; d++) o[d] = 0.f;

    const float* Kb = K + (size_t)b * HWk * Dm + h * HD;
    const float* Vb = V + (size_t)b * HWk * Dm + h * HD;

    const int kr = tid >> 2;        // tile row to load
    const int c8 = (tid & 3) * 8;   // 8 floats per thread

    for (int j0 = 0; j0 < HWk; j0 += 64) {
        // load K/V tiles (coalesced, float4)
        {
            const float* kp = Kb + (size_t)(j0 + kr) * Dm + c8;
            const float* vp = Vb + (size_t)(j0 + kr) * Dm + c8;
            *(float4*)&Ks[kr][c8 + 0] = *(const float4*)(kp + 0);
            *(float4*)&Ks[kr][c8 + 4] = *(const float4*)(kp + 4);
            *(float4*)&Vs[kr][c8 + 0] = *(const float4*)(vp + 0);
            *(float4*)&Vs[kr][c8 + 4] = *(const float4*)(vp + 4);
        }
        __syncthreads();

        // scores for this thread's 16 keys: c = cc*4 + p
        float s[16];
        float tmax = -1e30f;
#pragma unroll
        for (int cc = 0; cc < 16; cc++) {
            const int c = (cc << 2) + p;
            const float4* k4 = (const float4*)&Ks[c][0];
            float acc = 0.f;
#pragma unroll
            for (int dd = 0; dd < 8; dd++) {
                float4 kv = k4[dd];
                acc += q[dd * 4 + 0] * kv.x + q[dd * 4 + 1] * kv.y
                     + q[dd * 4 + 2] * kv.z + q[dd * 4 + 3] * kv.w;
            }
            s[cc] = acc;
            tmax = fmaxf(tmax, acc);
        }

        // row max across the 4 partition threads (adjacent lanes)
        tmax = fmaxf(tmax, __shfl_xor_sync(0xffffffffu, tmax, 1));
        tmax = fmaxf(tmax, __shfl_xor_sync(0xffffffffu, tmax, 2));

        const float m_new = fmaxf(m_i, tmax);
        const float alpha = __expf(m_i - m_new);
        m_i = m_new;
        l_i *= alpha;
#pragma unroll
        for (int d = 0; d < HD; d++) o[d] *= alpha;

        // P*V accumulation over this thread's keys
#pragma unroll
        for (int cc = 0; cc < 16; cc++) {
            const float w = __expf(s[cc] - m_new);
            l_i += w;
            const int c = (cc << 2) + p;
            const float4* v4 = (const float4*)&Vs[c][0];
#pragma unroll
            for (int dd = 0; dd < 8; dd++) {
                float4 vv = v4[dd];
                o[dd * 4 + 0] += w * vv.x; o[dd * 4 + 1] += w * vv.y;
                o[dd * 4 + 2] += w * vv.z; o[dd * 4 + 3] += w * vv.w;
            }
        }
        __syncthreads();
    }

    // reduce l and o across the 4 partition threads
    l_i += __shfl_xor_sync(0xffffffffu, l_i, 1);
    l_i += __shfl_xor_sync(0xffffffffu, l_i, 2);
#pragma unroll
    for (int d = 0; d < HD; d++) {
        o[d] += __shfl_xor_sync(0xffffffffu, o[d], 1);
        o[d] += __shfl_xor_sync(0xffffffffu, o[d], 2);
    }

    const float inv = 1.f / l_i;
    float* optr = O + ((size_t)(b * Sq + q0 + r)) * Dm + h * HD + p * 8;
#pragma unroll
    for (int d = 0; d < 8; d++) optr[d] = o[p * 8 + d] * inv;
}

// ---------------------------------------------------------------------------
// Launch
// ---------------------------------------------------------------------------
extern "C" void kernel_launch(void* const* d_in, const int* in_sizes, int n_in,
                              void* d_out, int out_size)
{
    const float* query = (const float*)d_in[0];  // (B,S,D)
    const float* keyv  = (const float*)d_in[1];  // (B,D,H,W) = (B,D,HW)
    const float* Wq    = (const float*)d_in[2];
    const float* bq    = (const float*)d_in[3];
    const float* Wk    = (const float*)d_in[4];
    const float* bk    = (const float*)d_in[5];
    const float* Wv    = (const float*)d_in[6];
    const float* bv    = (const float*)d_in[7];
    const float* Wo    = (const float*)d_in[8];
    const float* bo    = (const float*)d_in[9];
    float* out = (float*)d_out;

    float *dQ, *dK, *dV, *dA;
    cudaGetSymbolAddress((void**)&dQ, g_Q);
    cudaGetSymbolAddress((void**)&dK, g_K);
    cudaGetSymbolAddress((void**)&dV, g_V);
    cudaGetSymbolAddress((void**)&dA, g_A);

    // Q projection: M = B*S = 2048
    {
        dim3 grid(Dm / 64, (Bsz * Sq) / 64);
        gemm_nt_bias<<<grid, 256>>>(query, Wq, bq, dQ);
    }
    // K,V projections: per-batch transposed input
    {
        dim3 grid(Dm / 64, HWk / 64, Bsz);
        gemm_kv_bias<<<grid, 256>>>(keyv, Wk, bk, dK);
        gemm_kv_bias<<<grid, 256>>>(keyv, Wv, bv, dV);
    }
    // attention
    {
        dim3 grid(Sq / 64, NH, Bsz);
        attn_kernel<<<grid, 256>>>(dQ, dK, dV, dA);
    }
    // output projection -> d_out
    {
        dim3 grid(Dm / 64, (Bsz * Sq) / 64);
        gemm_nt_bias<<<grid, 256>>>(dA, Wo, bo, out);
    }
}

// round 2
// speedup vs baseline: 2.4480x; 2.4480x over previous
#include <cuda_runtime.h>
#include <cuda_bf16.h>
#include <cstdint>

// Problem dims (fixed)
#define Dm   256
#define Bsz  4
#define Sq   512
#define HWk  4096
#define NH   8
#define HD   32

// Scratch (no cudaMalloc allowed)
__device__ float g_Q[Bsz * Sq * Dm];      // (B,S,D) projected Q
__device__ float g_K[Bsz * HWk * Dm];     // (B,HW,D)
__device__ float g_V[Bsz * HWk * Dm];     // (B,HW,D)
__device__ float g_A[Bsz * Sq * Dm];      // attention output (B,S,D)

// ---------------------------------------------------------------------------
// GEMM: C[m,n] = sum_k A[m,k] * W[n,k] + bias[n]   (FP32 SIMT, unchanged)
// ---------------------------------------------------------------------------
__global__ __launch_bounds__(256)
void gemm_nt_bias(const float* __restrict__ A, const float* __restrict__ W,
                  const float* __restrict__ bias, float* __restrict__ C)
{
    __shared__ float As[16][64];
    __shared__ float Ws[16][64];

    const int bm = blockIdx.y * 64;
    const int bn = blockIdx.x * 64;
    const int tid = threadIdx.x;

    const int tr = (tid >> 4) << 2;
    const int tc = (tid & 15) << 2;

    const int lr = tid >> 2;
    const int lc = (tid & 3) << 2;

    float acc[4][4];
#pragma unroll
    for (int i = 0; i < 4; i++)
#pragma unroll
        for (int j = 0; j < 4; j++) acc[i][j] = 0.f;

    for (int k0 = 0; k0 < Dm; k0 += 16) {
        float4 av = *(const float4*)(A + (size_t)(bm + lr) * Dm + k0 + lc);
        As[lc + 0][lr] = av.x; As[lc + 1][lr] = av.y;
        As[lc + 2][lr] = av.z; As[lc + 3][lr] = av.w;
        float4 wv = *(const float4*)(W + (size_t)(bn + lr) * Dm + k0 + lc);
        Ws[lc + 0][lr] = wv.x; Ws[lc + 1][lr] = wv.y;
        Ws[lc + 2][lr] = wv.z; Ws[lc + 3][lr] = wv.w;
        __syncthreads();

#pragma unroll
        for (int k = 0; k < 16; k++) {
            float4 a4 = *(const float4*)&As[k][tr];
            float4 b4 = *(const float4*)&Ws[k][tc];
            float a[4] = {a4.x, a4.y, a4.z, a4.w};
            float b[4] = {b4.x, b4.y, b4.z, b4.w};
#pragma unroll
            for (int i = 0; i < 4; i++)
#pragma unroll
                for (int j = 0; j < 4; j++)
                    acc[i][j] += a[i] * b[j];
        }
        __syncthreads();
    }

#pragma unroll
    for (int i = 0; i < 4; i++) {
#pragma unroll
        for (int j = 0; j < 4; j++) {
            C[(size_t)(bm + tr + i) * Dm + bn + tc + j] = acc[i][j] + bias[bn + tc + j];
        }
    }
}

// ---------------------------------------------------------------------------
// KV projection GEMM (transposed input), unchanged
// ---------------------------------------------------------------------------
__global__ __launch_bounds__(256)
void gemm_kv_bias(const float* __restrict__ KVin, const float* __restrict__ W,
                  const float* __restrict__ bias, float* __restrict__ C)
{
    const int b = blockIdx.z;
    const float* A = KVin + (size_t)b * Dm * HWk;
    float* Cb = C + (size_t)b * HWk * Dm;

    __shared__ float As[16][64];
    __shared__ float Ws[16][64];

    const int bm = blockIdx.y * 64;
    const int bn = blockIdx.x * 64;
    const int tid = threadIdx.x;

    const int tr = (tid >> 4) << 2;
    const int tc = (tid & 15) << 2;

    const int kr = tid >> 4;
    const int m4 = (tid & 15) << 2;
    const int lr = tid >> 2;
    const int lc = (tid & 3) << 2;

    float acc[4][4];
#pragma unroll
    for (int i = 0; i < 4; i++)
#pragma unroll
        for (int j = 0; j < 4; j++) acc[i][j] = 0.f;

    for (int k0 = 0; k0 < Dm; k0 += 16) {
        float4 av = *(const float4*)(A + (size_t)(k0 + kr) * HWk + bm + m4);
        *(float4*)&As[kr][m4] = av;
        float4 wv = *(const float4*)(W + (size_t)(bn + lr) * Dm + k0 + lc);
        Ws[lc + 0][lr] = wv.x; Ws[lc + 1][lr] = wv.y;
        Ws[lc + 2][lr] = wv.z; Ws[lc + 3][lr] = wv.w;
        __syncthreads();

#pragma unroll
        for (int k = 0; k < 16; k++) {
            float4 a4 = *(const float4*)&As[k][tr];
            float4 b4 = *(const float4*)&Ws[k][tc];
            float a[4] = {a4.x, a4.y, a4.z, a4.w};
            float bb[4] = {b4.x, b4.y, b4.z, b4.w};
#pragma unroll
            for (int i = 0; i < 4; i++)
#pragma unroll
                for (int j = 0; j < 4; j++)
                    acc[i][j] += a[i] * bb[j];
        }
        __syncthreads();
    }

#pragma unroll
    for (int i = 0; i < 4; i++) {
#pragma unroll
        for (int j = 0; j < 4; j++) {
            Cb[(size_t)(bm + tr + i) * Dm + bn + tc + j] = acc[i][j] + bias[bn + tc + j];
        }
    }
}

// ---------------------------------------------------------------------------
// tf32 tensor-core flash attention
// CTA = (b, h, 64-query block), 4 warps x 16 queries each.
// S = Q K^T via mma.m16n8k8.tf32 (K tile tf32 in SMEM, stride 36 -> no
// bank conflicts on b-frag loads). Online softmax on fragments.
// P staged via per-warp SMEM (c-layout -> a-layout), O = P V via mma
// (V tile tf32 in SMEM, stride 40 -> conflict-free b-frag loads).
// ---------------------------------------------------------------------------
#define KST 36
#define VST 40
#define PST 68

__device__ __forceinline__ uint32_t cvt_tf32(float x) {
    uint32_t r;
    asm("cvt.rna.tf32.f32 %0, %1;" : "=r"(r) : "f"(x));
    return r;
}

__device__ __forceinline__ void mma_tf32(float c[4], const uint32_t a[4],
                                         uint32_t b0, uint32_t b1) {
    asm volatile(
        "mma.sync.aligned.m16n8k8.row.col.f32.tf32.tf32.f32 "
        "{%0,%1,%2,%3}, {%4,%5,%6,%7}, {%8,%9}, {%0,%1,%2,%3};"
        : "+f"(c[0]), "+f"(c[1]), "+f"(c[2]), "+f"(c[3])
        : "r"(a[0]), "r"(a[1]), "r"(a[2]), "r"(a[3]), "r"(b0), "r"(b1));
}

__global__ __launch_bounds__(128)
void attn_mma(const float* __restrict__ Q, const float* __restrict__ K,
              const float* __restrict__ V, float* __restrict__ O)
{
    const int h  = blockIdx.y;
    const int b  = blockIdx.z;
    const int q0 = blockIdx.x * 64;

    __shared__ uint32_t Ks[64][KST];
    __shared__ uint32_t Vs[64][VST];
    __shared__ uint32_t Ps[4][16][PST];

    const int tid  = threadIdx.x;
    const int warp = tid >> 5;
    const int lane = tid & 31;
    const int gid  = lane >> 2;   // group id (row within fragment)
    const int tig  = lane & 3;    // thread in group

    const float scale = 0.17677669529663687f;  // 1/sqrt(32)

    // ---- Q a-fragments (4 k-blocks x 4 regs), pre-scaled, tf32 ----
    uint32_t qa[4][4];
    {
        const float* Qb = Q + ((size_t)(b * Sq + q0 + warp * 16)) * Dm + h * HD;
#pragma unroll
        for (int kb = 0; kb < 4; kb++) {
            qa[kb][0] = cvt_tf32(Qb[(size_t)gid       * Dm + kb * 8 + tig    ] * scale);
            qa[kb][1] = cvt_tf32(Qb[(size_t)(gid + 8) * Dm + kb * 8 + tig    ] * scale);
            qa[kb][2] = cvt_tf32(Qb[(size_t)gid       * Dm + kb * 8 + tig + 4] * scale);
            qa[kb][3] = cvt_tf32(Qb[(size_t)(gid + 8) * Dm + kb * 8 + tig + 4] * scale);
        }
    }

    float m_lo = -1e30f, m_hi = -1e30f;
    float l_lo = 0.f,    l_hi = 0.f;
    float o[4][4];
#pragma unroll
    for (int nb = 0; nb < 4; nb++)
#pragma unroll
        for (int i = 0; i < 4; i++) o[nb][i] = 0.f;

    const float* Kb = K + (size_t)b * HWk * Dm + h * HD;
    const float* Vb = V + (size_t)b * HWk * Dm + h * HD;

    // tile-load mapping: 128 threads x 16 floats = 64 rows x 32 cols
    const int lrow = tid >> 1;
    const int lcol = (tid & 1) * 16;

    for (int j0 = 0; j0 < HWk; j0 += 64) {
        __syncthreads();   // protect Ks/Vs from previous iteration's readers
        {
            const float* kp = Kb + (size_t)(j0 + lrow) * Dm + lcol;
            const float* vp = Vb + (size_t)(j0 + lrow) * Dm + lcol;
#pragma unroll
            for (int i = 0; i < 16; i += 4) {
                float4 kv = *(const float4*)(kp + i);
                float4 vv = *(const float4*)(vp + i);
                Ks[lrow][lcol + i + 0] = cvt_tf32(kv.x);
                Ks[lrow][lcol + i + 1] = cvt_tf32(kv.y);
                Ks[lrow][lcol + i + 2] = cvt_tf32(kv.z);
                Ks[lrow][lcol + i + 3] = cvt_tf32(kv.w);
                Vs[lrow][lcol + i + 0] = cvt_tf32(vv.x);
                Vs[lrow][lcol + i + 1] = cvt_tf32(vv.y);
                Vs[lrow][lcol + i + 2] = cvt_tf32(vv.z);
                Vs[lrow][lcol + i + 3] = cvt_tf32(vv.w);
            }
        }
        __syncthreads();

        // ---- S = Q K^T : 8 n-blocks (64 keys) x 4 k-blocks (32 dims) ----
        float s[8][4];
#pragma unroll
        for (int nb = 0; nb < 8; nb++)
#pragma unroll
            for (int i = 0; i < 4; i++) s[nb][i] = 0.f;

#pragma unroll
        for (int kb = 0; kb < 4; kb++) {
#pragma unroll
            for (int nb = 0; nb < 8; nb++) {
                uint32_t b0 = Ks[nb * 8 + gid][kb * 8 + tig];
                uint32_t b1 = Ks[nb * 8 + gid][kb * 8 + tig + 4];
                mma_tf32(s[nb], qa[kb], b0, b1);
            }
        }

        // ---- online softmax ----
        float tmax_lo = -1e30f, tmax_hi = -1e30f;
#pragma unroll
        for (int nb = 0; nb < 8; nb++) {
            tmax_lo = fmaxf(tmax_lo, fmaxf(s[nb][0], s[nb][1]));
            tmax_hi = fmaxf(tmax_hi, fmaxf(s[nb][2], s[nb][3]));
        }
        tmax_lo = fmaxf(tmax_lo, __shfl_xor_sync(0xffffffffu, tmax_lo, 1));
        tmax_lo = fmaxf(tmax_lo, __shfl_xor_sync(0xffffffffu, tmax_lo, 2));
        tmax_hi = fmaxf(tmax_hi, __shfl_xor_sync(0xffffffffu, tmax_hi, 1));
        tmax_hi = fmaxf(tmax_hi, __shfl_xor_sync(0xffffffffu, tmax_hi, 2));

        const float mn_lo = fmaxf(m_lo, tmax_lo);
        const float mn_hi = fmaxf(m_hi, tmax_hi);
        const float al_lo = __expf(m_lo - mn_lo);
        const float al_hi = __expf(m_hi - mn_hi);
        m_lo = mn_lo; m_hi = mn_hi;
        l_lo *= al_lo; l_hi *= al_hi;
#pragma unroll
        for (int nb = 0; nb < 4; nb++) {
            o[nb][0] *= al_lo; o[nb][1] *= al_lo;
            o[nb][2] *= al_hi; o[nb][3] *= al_hi;
        }

        // exp + store P (tf32) to per-warp SMEM
#pragma unroll
        for (int nb = 0; nb < 8; nb++) {
            float p0 = __expf(s[nb][0] - mn_lo);
            float p1 = __expf(s[nb][1] - mn_lo);
            float p2 = __expf(s[nb][2] - mn_hi);
            float p3 = __expf(s[nb][3] - mn_hi);
            l_lo += p0 + p1;
            l_hi += p2 + p3;
            Ps[warp][gid    ][nb * 8 + 2 * tig    ] = cvt_tf32(p0);
            Ps[warp][gid    ][nb * 8 + 2 * tig + 1] = cvt_tf32(p1);
            Ps[warp][gid + 8][nb * 8 + 2 * tig    ] = cvt_tf32(p2);
            Ps[warp][gid + 8][nb * 8 + 2 * tig + 1] = cvt_tf32(p3);
        }
        __syncwarp();

        // ---- O += P V : 8 k-blocks (64 keys) x 4 n-blocks (32 dims) ----
#pragma unroll
        for (int kb = 0; kb < 8; kb++) {
            uint32_t pa[4];
            pa[0] = Ps[warp][gid    ][kb * 8 + tig    ];
            pa[1] = Ps[warp][gid + 8][kb * 8 + tig    ];
            pa[2] = Ps[warp][gid    ][kb * 8 + tig + 4];
            pa[3] = Ps[warp][gid + 8][kb * 8 + tig + 4];
#pragma unroll
            for (int nb = 0; nb < 4; nb++) {
                uint32_t b0 = Vs[kb * 8 + tig    ][nb * 8 + gid];
                uint32_t b1 = Vs[kb * 8 + tig + 4][nb * 8 + gid];
                mma_tf32(o[nb], pa, b0, b1);
            }
        }
        __syncwarp();
    }

    // ---- final reduce of l across the 4-lane group ----
    l_lo += __shfl_xor_sync(0xffffffffu, l_lo, 1);
    l_lo += __shfl_xor_sync(0xffffffffu, l_lo, 2);
    l_hi += __shfl_xor_sync(0xffffffffu, l_hi, 1);
    l_hi += __shfl_xor_sync(0xffffffffu, l_hi, 2);
    const float inv_lo = 1.f / l_lo;
    const float inv_hi = 1.f / l_hi;

    float* Og = O + ((size_t)(b * Sq + q0 + warp * 16)) * Dm + h * HD;
#pragma unroll
    for (int nb = 0; nb < 4; nb++) {
        float2 lo = make_float2(o[nb][0] * inv_lo, o[nb][1] * inv_lo);
        float2 hi = make_float2(o[nb][2] * inv_hi, o[nb][3] * inv_hi);
        *(float2*)(Og + (size_t)gid       * Dm + nb * 8 + 2 * tig) = lo;
        *(float2*)(Og + (size_t)(gid + 8) * Dm + nb * 8 + 2 * tig) = hi;
    }
}

// ---------------------------------------------------------------------------
// Launch
// ---------------------------------------------------------------------------
extern "C" void kernel_launch(void* const* d_in, const int* in_sizes, int n_in,
                              void* d_out, int out_size)
{
    const float* query = (const float*)d_in[0];
    const float* keyv  = (const float*)d_in[1];
    const float* Wq    = (const float*)d_in[2];
    const float* bq    = (const float*)d_in[3];
    const float* Wk    = (const float*)d_in[4];
    const float* bk    = (const float*)d_in[5];
    const float* Wv    = (const float*)d_in[6];
    const float* bv    = (const float*)d_in[7];
    const float* Wo    = (const float*)d_in[8];
    const float* bo    = (const float*)d_in[9];
    float* out = (float*)d_out;

    float *dQ, *dK, *dV, *dA;
    cudaGetSymbolAddress((void**)&dQ, g_Q);
    cudaGetSymbolAddress((void**)&dK, g_K);
    cudaGetSymbolAddress((void**)&dV, g_V);
    cudaGetSymbolAddress((void**)&dA, g_A);

    {
        dim3 grid(Dm / 64, (Bsz * Sq) / 64);
        gemm_nt_bias<<<grid, 256>>>(query, Wq, bq, dQ);
    }
    {
        dim3 grid(Dm / 64, HWk / 64, Bsz);
        gemm_kv_bias<<<grid, 256>>>(keyv, Wk, bk, dK);
        gemm_kv_bias<<<grid, 256>>>(keyv, Wv, bv, dV);
    }
    {
        dim3 grid(Sq / 64, NH, Bsz);
        attn_mma<<<grid, 128>>>(dQ, dK, dV, dA);
    }
    {
        dim3 grid(Dm / 64, (Bsz * Sq) / 64);
        gemm_nt_bias<<<grid, 256>>>(dA, Wo, bo, out);
    }
}

// round 3
// speedup vs baseline: 2.8010x; 1.1442x over previous
#include <cuda_runtime.h>
#include <cuda_bf16.h>
#include <cstdint>

// Problem dims (fixed)
#define Dm   256
#define Bsz  4
#define Sq   512
#define HWk  4096
#define NH   8
#define HD   32
#define NSPLIT 2

// Scratch (no cudaMalloc allowed)
__device__ float g_Q[Bsz * Sq * Dm];
__device__ float g_K[Bsz * HWk * Dm];
__device__ float g_V[Bsz * HWk * Dm];
__device__ float g_A[Bsz * Sq * Dm];
// attention split partials
__device__ float g_Po[Bsz * NH * NSPLIT * Sq * HD];
__device__ float g_Pm[Bsz * NH * NSPLIT * Sq];
__device__ float g_Pl[Bsz * NH * NSPLIT * Sq];

__device__ __forceinline__ uint32_t cvt_tf32(float x) {
    uint32_t r;
    asm("cvt.rna.tf32.f32 %0, %1;" : "=r"(r) : "f"(x));
    return r;
}

__device__ __forceinline__ void mma_tf32(float c[4], const uint32_t a[4],
                                         uint32_t b0, uint32_t b1) {
    asm volatile(
        "mma.sync.aligned.m16n8k8.row.col.f32.tf32.tf32.f32 "
        "{%0,%1,%2,%3}, {%4,%5,%6,%7}, {%8,%9}, {%0,%1,%2,%3};"
        : "+f"(c[0]), "+f"(c[1]), "+f"(c[2]), "+f"(c[3])
        : "r"(a[0]), "r"(a[1]), "r"(a[2]), "r"(a[3]), "r"(b0), "r"(b1));
}

// ---------------------------------------------------------------------------
// tf32 tensor-core GEMM: C[m,n] = sum_k A[m,k] * W[n,k] + bias[n]
// BM=128, BN=128, BK=32, 8 warps (4m x 2n), warp tile 32x64.
// TRANS=0: A row-major MxK (lda = 256). TRANS=1: A is K x M (lda = HWk).
// ---------------------------------------------------------------------------
#define MPAD 132
#define WPAD 36

template<int TRANS>
__global__ __launch_bounds__(256)
void gemm_tf32(const float* __restrict__ A, const float* __restrict__ W,
               const float* __restrict__ bias, float* __restrict__ C,
               int lda)
{
    __shared__ uint32_t As[32][MPAD];   // [k][m]
    __shared__ uint32_t Ws[128][WPAD];  // [n][k]

    const int bm = blockIdx.x * 128;
    const int bn = blockIdx.y * 128;
    const int tid  = threadIdx.x;
    const int warp = tid >> 5;
    const int lane = tid & 31;
    const int gid  = lane >> 2;
    const int tig  = lane & 3;
    const int wm = (warp >> 1) * 32;
    const int wn = (warp & 1) * 64;

    float acc[2][8][4];
#pragma unroll
    for (int mf = 0; mf < 2; mf++)
#pragma unroll
        for (int nb = 0; nb < 8; nb++)
#pragma unroll
            for (int j = 0; j < 4; j++) acc[mf][nb][j] = 0.f;

    // load mappings
    const int rr = tid >> 1;          // 0..127 (row-major A rows / W rows)
    const int kc = (tid & 1) * 16;    // 0,16
    const int kk = tid >> 3;          // 0..31 (trans A k-row)
    const int mc = (tid & 7) * 16;    // 0..112

    for (int k0 = 0; k0 < Dm; k0 += 32) {
        __syncthreads();
        if (TRANS) {
            // A[k][m] in gmem, coalesced along m
#pragma unroll
            for (int i = 0; i < 4; i++) {
                float4 v = *(const float4*)(A + (size_t)(k0 + kk) * lda + bm + mc + 4 * i);
                uint4 u;
                u.x = cvt_tf32(v.x); u.y = cvt_tf32(v.y);
                u.z = cvt_tf32(v.z); u.w = cvt_tf32(v.w);
                *(uint4*)&As[kk][mc + 4 * i] = u;
            }
        } else {
            // A[m][k] row-major; transpose into As[k][m]
#pragma unroll
            for (int i = 0; i < 4; i++) {
                float4 v = *(const float4*)(A + (size_t)(bm + rr) * lda + k0 + kc + 4 * i);
                As[kc + 4 * i + 0][rr] = cvt_tf32(v.x);
                As[kc + 4 * i + 1][rr] = cvt_tf32(v.y);
                As[kc + 4 * i + 2][rr] = cvt_tf32(v.z);
                As[kc + 4 * i + 3][rr] = cvt_tf32(v.w);
            }
        }
        // W[n][k] row-major
#pragma unroll
        for (int i = 0; i < 4; i++) {
            float4 v = *(const float4*)(W + (size_t)(bn + rr) * Dm + k0 + kc + 4 * i);
            uint4 u;
            u.x = cvt_tf32(v.x); u.y = cvt_tf32(v.y);
            u.z = cvt_tf32(v.z); u.w = cvt_tf32(v.w);
            *(uint4*)&Ws[rr][kc + 4 * i] = u;
        }
        __syncthreads();

#pragma unroll
        for (int kb = 0; kb < 4; kb++) {
            uint32_t a[2][4];
#pragma unroll
            for (int mf = 0; mf < 2; mf++) {
                a[mf][0] = As[kb * 8 + tig    ][wm + mf * 16 + gid    ];
                a[mf][1] = As[kb * 8 + tig    ][wm + mf * 16 + gid + 8];
                a[mf][2] = As[kb * 8 + tig + 4][wm + mf * 16 + gid    ];
                a[mf][3] = As[kb * 8 + tig + 4][wm + mf * 16 + gid + 8];
            }
#pragma unroll
            for (int nb = 0; nb < 8; nb++) {
                uint32_t b0 = Ws[wn + nb * 8 + gid][kb * 8 + tig    ];
                uint32_t b1 = Ws[wn + nb * 8 + gid][kb * 8 + tig + 4];
                mma_tf32(acc[0][nb], a[0], b0, b1);
                mma_tf32(acc[1][nb], a[1], b0, b1);
            }
        }
    }

    // epilogue: bias + store
#pragma unroll
    for (int mf = 0; mf < 2; mf++) {
        const int row = bm + wm + mf * 16 + gid;
#pragma unroll
        for (int nb = 0; nb < 8; nb++) {
            const int col = bn + wn + nb * 8 + 2 * tig;
            const float b0 = bias[col], b1 = bias[col + 1];
            *(float2*)(C + (size_t)row * Dm + col) =
                make_float2(acc[mf][nb][0] + b0, acc[mf][nb][1] + b1);
            *(float2*)(C + (size_t)(row + 8) * Dm + col) =
                make_float2(acc[mf][nb][2] + b0, acc[mf][nb][3] + b1);
        }
    }
}

// ---------------------------------------------------------------------------
// tf32 flash attention, split-KV. CTA = (qblock 64, head, b*2+split).
// 4 warps x 16 queries. S c-frag reused directly as PV a-frag via key
// permutation (phys key 2*tig/2*tig+1), V SMEM rows addressed accordingly.
// Writes unnormalized partial O + (m, l) per row.
// ---------------------------------------------------------------------------
#define KST 36
#define VST 36

__global__ __launch_bounds__(128)
void attn_mma(const float* __restrict__ Q, const float* __restrict__ K,
              const float* __restrict__ V, float* __restrict__ Po,
              float* __restrict__ Pm, float* __restrict__ Pl)
{
    const int h  = blockIdx.y;
    const int bz = blockIdx.z;
    const int b  = bz >> 1;
    const int sp = bz & 1;
    const int q0 = blockIdx.x * 64;

    __shared__ uint32_t Ks[64][KST];
    __shared__ uint32_t Vs[64][VST];

    const int tid  = threadIdx.x;
    const int warp = tid >> 5;
    const int lane = tid & 31;
    const int gid  = lane >> 2;
    const int tig  = lane & 3;

    const float scale = 0.17677669529663687f;  // 1/sqrt(32)

    uint32_t qa[4][4];
    {
        const float* Qb = Q + ((size_t)(b * Sq + q0 + warp * 16)) * Dm + h * HD;
#pragma unroll
        for (int kb = 0; kb < 4; kb++) {
            qa[kb][0] = cvt_tf32(Qb[(size_t)gid       * Dm + kb * 8 + tig    ] * scale);
            qa[kb][1] = cvt_tf32(Qb[(size_t)(gid + 8) * Dm + kb * 8 + tig    ] * scale);
            qa[kb][2] = cvt_tf32(Qb[(size_t)gid       * Dm + kb * 8 + tig + 4] * scale);
            qa[kb][3] = cvt_tf32(Qb[(size_t)(gid + 8) * Dm + kb * 8 + tig + 4] * scale);
        }
    }

    float m_lo = -1e30f, m_hi = -1e30f;
    float l_lo = 0.f,    l_hi = 0.f;
    float o[4][4];
#pragma unroll
    for (int nb = 0; nb < 4; nb++)
#pragma unroll
        for (int i = 0; i < 4; i++) o[nb][i] = 0.f;

    const float* Kb = K + (size_t)b * HWk * Dm + h * HD;
    const float* Vb = V + (size_t)b * HWk * Dm + h * HD;

    const int lrow = tid >> 1;
    const int lcol = (tid & 1) * 16;

    const int jbeg = sp * (HWk / NSPLIT);
    const int jend = jbeg + (HWk / NSPLIT);

    for (int j0 = jbeg; j0 < jend; j0 += 64) {
        __syncthreads();
        {
            const float* kp = Kb + (size_t)(j0 + lrow) * Dm + lcol;
            const float* vp = Vb + (size_t)(j0 + lrow) * Dm + lcol;
#pragma unroll
            for (int i = 0; i < 16; i += 4) {
                float4 kv = *(const float4*)(kp + i);
                float4 vv = *(const float4*)(vp + i);
                uint4 ku, vu;
                ku.x = cvt_tf32(kv.x); ku.y = cvt_tf32(kv.y);
                ku.z = cvt_tf32(kv.z); ku.w = cvt_tf32(kv.w);
                vu.x = cvt_tf32(vv.x); vu.y = cvt_tf32(vv.y);
                vu.z = cvt_tf32(vv.z); vu.w = cvt_tf32(vv.w);
                *(uint4*)&Ks[lrow][lcol + i] = ku;
                *(uint4*)&Vs[lrow][lcol + i] = vu;
            }
        }
        __syncthreads();

        // ---- S = Q K^T ----
        float s[8][4];
#pragma unroll
        for (int nb = 0; nb < 8; nb++)
#pragma unroll
            for (int i = 0; i < 4; i++) s[nb][i] = 0.f;

#pragma unroll
        for (int kb = 0; kb < 4; kb++) {
#pragma unroll
            for (int nb = 0; nb < 8; nb++) {
                uint32_t b0 = Ks[nb * 8 + gid][kb * 8 + tig];
                uint32_t b1 = Ks[nb * 8 + gid][kb * 8 + tig + 4];
                mma_tf32(s[nb], qa[kb], b0, b1);
            }
        }

        // ---- online softmax ----
        float tmax_lo = -1e30f, tmax_hi = -1e30f;
#pragma unroll
        for (int nb = 0; nb < 8; nb++) {
            tmax_lo = fmaxf(tmax_lo, fmaxf(s[nb][0], s[nb][1]));
            tmax_hi = fmaxf(tmax_hi, fmaxf(s[nb][2], s[nb][3]));
        }
        tmax_lo = fmaxf(tmax_lo, __shfl_xor_sync(0xffffffffu, tmax_lo, 1));
        tmax_lo = fmaxf(tmax_lo, __shfl_xor_sync(0xffffffffu, tmax_lo, 2));
        tmax_hi = fmaxf(tmax_hi, __shfl_xor_sync(0xffffffffu, tmax_hi, 1));
        tmax_hi = fmaxf(tmax_hi, __shfl_xor_sync(0xffffffffu, tmax_hi, 2));

        const float mn_lo = fmaxf(m_lo, tmax_lo);
        const float mn_hi = fmaxf(m_hi, tmax_hi);
        const float al_lo = __expf(m_lo - mn_lo);
        const float al_hi = __expf(m_hi - mn_hi);
        m_lo = mn_lo; m_hi = mn_hi;
        l_lo *= al_lo; l_hi *= al_hi;
#pragma unroll
        for (int nb = 0; nb < 4; nb++) {
            o[nb][0] *= al_lo; o[nb][1] *= al_lo;
            o[nb][2] *= al_hi; o[nb][3] *= al_hi;
        }

        // ---- exp + O += P V (c-frag used directly as a-frag; V rows permuted) ----
#pragma unroll
        for (int kb = 0; kb < 8; kb++) {
            const float p0 = __expf(s[kb][0] - mn_lo);  // row gid,   phys key kb*8+2tig
            const float p1 = __expf(s[kb][1] - mn_lo);  // row gid,   phys key kb*8+2tig+1
            const float p2 = __expf(s[kb][2] - mn_hi);  // row gid+8, phys key kb*8+2tig
            const float p3 = __expf(s[kb][3] - mn_hi);
            l_lo += p0 + p1;
            l_hi += p2 + p3;
            uint32_t pa[4];
            pa[0] = cvt_tf32(p0);   // a[gid][k_mma=tig]      <-> phys 2tig
            pa[1] = cvt_tf32(p2);   // a[gid+8][k_mma=tig]
            pa[2] = cvt_tf32(p1);   // a[gid][k_mma=tig+4]    <-> phys 2tig+1
            pa[3] = cvt_tf32(p3);
#pragma unroll
            for (int nb = 0; nb < 4; nb++) {
                uint32_t b0 = Vs[kb * 8 + 2 * tig    ][nb * 8 + gid];
                uint32_t b1 = Vs[kb * 8 + 2 * tig + 1][nb * 8 + gid];
                mma_tf32(o[nb], pa, b0, b1);
            }
        }
    }

    // reduce l across the 4-lane group
    l_lo += __shfl_xor_sync(0xffffffffu, l_lo, 1);
    l_lo += __shfl_xor_sync(0xffffffffu, l_lo, 2);
    l_hi += __shfl_xor_sync(0xffffffffu, l_hi, 1);
    l_hi += __shfl_xor_sync(0xffffffffu, l_hi, 2);

    // store partials (unnormalized)
    const int row0 = (((b * NH + h) * NSPLIT) + sp) * Sq + q0 + warp * 16;
#pragma unroll
    for (int nb = 0; nb < 4; nb++) {
        *(float2*)(Po + (size_t)(row0 + gid)     * HD + nb * 8 + 2 * tig) =
            make_float2(o[nb][0], o[nb][1]);
        *(float2*)(Po + (size_t)(row0 + gid + 8) * HD + nb * 8 + 2 * tig) =
            make_float2(o[nb][2], o[nb][3]);
    }
    if (tig == 0) {
        Pm[row0 + gid]     = m_lo;  Pl[row0 + gid]     = l_lo;
        Pm[row0 + gid + 8] = m_hi;  Pl[row0 + gid + 8] = l_hi;
    }
}

// ---------------------------------------------------------------------------
// combine split partials -> (B,S,D)
// ---------------------------------------------------------------------------
__global__ __launch_bounds__(256)
void attn_combine(const float* __restrict__ Po, const float* __restrict__ Pm,
                  const float* __restrict__ Pl, float* __restrict__ Aout)
{
    const int t = blockIdx.x * 256 + threadIdx.x;  // < 16384*4
    const int row = t >> 2;
    const int dc  = (t & 3) * 8;
    const int bh  = row / Sq;
    const int q   = row % Sq;
    const int b   = bh / NH;
    const int h   = bh % NH;

    const size_t i0 = (size_t)(bh * NSPLIT + 0) * Sq + q;
    const size_t i1 = (size_t)(bh * NSPLIT + 1) * Sq + q;
    const float m0 = Pm[i0], m1 = Pm[i1];
    const float l0 = Pl[i0], l1 = Pl[i1];
    const float m  = fmaxf(m0, m1);
    const float w0 = __expf(m0 - m);
    const float w1 = __expf(m1 - m);
    const float inv = 1.f / (l0 * w0 + l1 * w1);

    const float* o0 = Po + i0 * HD + dc;
    const float* o1 = Po + i1 * HD + dc;
    float* out = Aout + ((size_t)(b * Sq + q)) * Dm + h * HD + dc;
#pragma unroll
    for (int i = 0; i < 8; i += 4) {
        float4 a = *(const float4*)(o0 + i);
        float4 c = *(const float4*)(o1 + i);
        float4 r;
        r.x = (a.x * w0 + c.x * w1) * inv;
        r.y = (a.y * w0 + c.y * w1) * inv;
        r.z = (a.z * w0 + c.z * w1) * inv;
        r.w = (a.w * w0 + c.w * w1) * inv;
        *(float4*)(out + i) = r;
    }
}

// ---------------------------------------------------------------------------
// Launch
// ---------------------------------------------------------------------------
extern "C" void kernel_launch(void* const* d_in, const int* in_sizes, int n_in,
                              void* d_out, int out_size)
{
    const float* query = (const float*)d_in[0];
    const float* keyv  = (const float*)d_in[1];
    const float* Wq    = (const float*)d_in[2];
    const float* bq    = (const float*)d_in[3];
    const float* Wk    = (const float*)d_in[4];
    const float* bk    = (const float*)d_in[5];
    const float* Wv    = (const float*)d_in[6];
    const float* bv    = (const float*)d_in[7];
    const float* Wo    = (const float*)d_in[8];
    const float* bo    = (const float*)d_in[9];
    float* out = (float*)d_out;

    float *dQ, *dK, *dV, *dA, *dPo, *dPm, *dPl;
    cudaGetSymbolAddress((void**)&dQ, g_Q);
    cudaGetSymbolAddress((void**)&dK, g_K);
    cudaGetSymbolAddress((void**)&dV, g_V);
    cudaGetSymbolAddress((void**)&dA, g_A);
    cudaGetSymbolAddress((void**)&dPo, g_Po);
    cudaGetSymbolAddress((void**)&dPm, g_Pm);
    cudaGetSymbolAddress((void**)&dPl, g_Pl);

    // Q projection: M = B*S = 2048 (contiguous)
    {
        dim3 grid((Bsz * Sq) / 128, Dm / 128);
        gemm_tf32<0><<<grid, 256>>>(query, Wq, bq, dQ, Dm);
    }
    // K,V projections: per-batch transposed input (A is D x HW)
    for (int b = 0; b < Bsz; b++) {
        dim3 grid(HWk / 128, Dm / 128);
        const float* Ab = keyv + (size_t)b * Dm * HWk;
        gemm_tf32<1><<<grid, 256>>>(Ab, Wk, bk, dK + (size_t)b * HWk * Dm, HWk);
        gemm_tf32<1><<<grid, 256>>>(Ab, Wv, bv, dV + (size_t)b * HWk * Dm, HWk);
    }
    // attention (split-KV)
    {
        dim3 grid(Sq / 64, NH, Bsz * NSPLIT);
        attn_mma<<<grid, 128>>>(dQ, dK, dV, dPo, dPm, dPl);
    }
    // combine
    {
        attn_combine<<<(Bsz * NH * Sq * 4) / 256, 256>>>(dPo, dPm, dPl, dA);
    }
    // output projection -> d_out
    {
        dim3 grid((Bsz * Sq) / 128, Dm / 128);
        gemm_tf32<0><<<grid, 256>>>(dA, Wo, bo, out, Dm);
    }
}

// round 4
// speedup vs baseline: 3.6706x; 1.3105x over previous
#include <cuda_runtime.h>
#include <cuda_bf16.h>
#include <cstdint>

// Problem dims (fixed)
#define Dm   256
#define Bsz  4
#define Sq   512
#define HWk  4096
#define NH   8
#define HD   32
#define NSPLIT 2

// Scratch (no cudaMalloc allowed)
__device__ float g_Q[Bsz * Sq * Dm];
__device__ float g_K[Bsz * HWk * Dm];
__device__ float g_V[Bsz * HWk * Dm];
__device__ float g_A[Bsz * Sq * Dm];
__device__ float g_Po[Bsz * NH * NSPLIT * Sq * HD];
__device__ float g_Pm[Bsz * NH * NSPLIT * Sq];
__device__ float g_Pl[Bsz * NH * NSPLIT * Sq];

__device__ __forceinline__ uint32_t cvt_tf32(float x) {
    uint32_t r;
    asm("cvt.rna.tf32.f32 %0, %1;" : "=r"(r) : "f"(x));
    return r;
}

__device__ __forceinline__ void mma_tf32(float c[4], const uint32_t a[4],
                                         uint32_t b0, uint32_t b1) {
    asm volatile(
        "mma.sync.aligned.m16n8k8.row.col.f32.tf32.tf32.f32 "
        "{%0,%1,%2,%3}, {%4,%5,%6,%7}, {%8,%9}, {%0,%1,%2,%3};"
        : "+f"(c[0]), "+f"(c[1]), "+f"(c[2]), "+f"(c[3])
        : "r"(a[0]), "r"(a[1]), "r"(a[2]), "r"(a[3]), "r"(b0), "r"(b1));
}

#define MPAD 132
#define WPAD 36

// ---------------------------------------------------------------------------
// FUSED KV projection: one launch, grid.z in [0,8): b = z>>1, K/V = z&1.
// C[b,m,n] = sum_k kv[b,k,m] * W[n,k] + bias[n].  Double-buffered mainloop.
// BM=128, BN=128, BK=32, 8 warps (4m x 2n), warp tile 32x64.
// ---------------------------------------------------------------------------
__global__ __launch_bounds__(256)
void gemm_kv_fused(const float* __restrict__ KVin,
                   const float* __restrict__ Wk, const float* __restrict__ bk,
                   const float* __restrict__ Wv, const float* __restrict__ bv,
                   float* __restrict__ Kout, float* __restrict__ Vout)
{
    const int z = blockIdx.z;
    const int b = z >> 1;
    const int isv = z & 1;
    const float* A    = KVin + (size_t)b * Dm * HWk;   // A[k][m], lda = HWk
    const float* W    = isv ? Wv : Wk;
    const float* bias = isv ? bv : bk;
    float* C = (isv ? Vout : Kout) + (size_t)b * HWk * Dm;

    __shared__ uint32_t As[2][32][MPAD];   // [k][m]
    __shared__ uint32_t Ws[2][128][WPAD];  // [n][k]

    const int bm = blockIdx.x * 128;
    const int bn = blockIdx.y * 128;
    const int tid  = threadIdx.x;
    const int warp = tid >> 5;
    const int lane = tid & 31;
    const int gid  = lane >> 2;
    const int tig  = lane & 3;
    const int wm = (warp >> 1) * 32;
    const int wn = (warp & 1) * 64;

    float acc[2][8][4];
#pragma unroll
    for (int mf = 0; mf < 2; mf++)
#pragma unroll
        for (int nb = 0; nb < 8; nb++)
#pragma unroll
            for (int j = 0; j < 4; j++) acc[mf][nb][j] = 0.f;

    const int kk = tid >> 3;          // 0..31 A k-row
    const int mc = (tid & 7) * 16;    // 0..120
    const int rr = tid >> 1;          // 0..127 W row
    const int kc = (tid & 1) * 16;    // 0,16

    float4 ra[4], rw[4];
    // preload tile 0
#pragma unroll
    for (int i = 0; i < 4; i++) {
        ra[i] = *(const float4*)(A + (size_t)kk * HWk + bm + mc + 4 * i);
        rw[i] = *(const float4*)(W + (size_t)(bn + rr) * Dm + kc + 4 * i);
    }
#pragma unroll
    for (int i = 0; i < 4; i++) {
        uint4 u;
        u.x = cvt_tf32(ra[i].x); u.y = cvt_tf32(ra[i].y);
        u.z = cvt_tf32(ra[i].z); u.w = cvt_tf32(ra[i].w);
        *(uint4*)&As[0][kk][mc + 4 * i] = u;
        uint4 w;
        w.x = cvt_tf32(rw[i].x); w.y = cvt_tf32(rw[i].y);
        w.z = cvt_tf32(rw[i].z); w.w = cvt_tf32(rw[i].w);
        *(uint4*)&Ws[0][rr][kc + 4 * i] = w;
    }
    __syncthreads();

#pragma unroll
    for (int it = 0; it < 8; it++) {
        const int cur = it & 1;
        const bool more = (it + 1) < 8;
        if (more) {
            const int k0n = (it + 1) * 32;
#pragma unroll
            for (int i = 0; i < 4; i++) {
                ra[i] = *(const float4*)(A + (size_t)(k0n + kk) * HWk + bm + mc + 4 * i);
                rw[i] = *(const float4*)(W + (size_t)(bn + rr) * Dm + k0n + kc + 4 * i);
            }
        }

#pragma unroll
        for (int kb = 0; kb < 4; kb++) {
            uint32_t a[2][4];
#pragma unroll
            for (int mf = 0; mf < 2; mf++) {
                a[mf][0] = As[cur][kb * 8 + tig    ][wm + mf * 16 + gid    ];
                a[mf][1] = As[cur][kb * 8 + tig    ][wm + mf * 16 + gid + 8];
                a[mf][2] = As[cur][kb * 8 + tig + 4][wm + mf * 16 + gid    ];
                a[mf][3] = As[cur][kb * 8 + tig + 4][wm + mf * 16 + gid + 8];
            }
#pragma unroll
            for (int nb = 0; nb < 8; nb++) {
                uint32_t b0 = Ws[cur][wn + nb * 8 + gid][kb * 8 + tig    ];
                uint32_t b1 = Ws[cur][wn + nb * 8 + gid][kb * 8 + tig + 4];
                mma_tf32(acc[0][nb], a[0], b0, b1);
                mma_tf32(acc[1][nb], a[1], b0, b1);
            }
        }

        if (more) {
            const int nxt = cur ^ 1;
#pragma unroll
            for (int i = 0; i < 4; i++) {
                uint4 u;
                u.x = cvt_tf32(ra[i].x); u.y = cvt_tf32(ra[i].y);
                u.z = cvt_tf32(ra[i].z); u.w = cvt_tf32(ra[i].w);
                *(uint4*)&As[nxt][kk][mc + 4 * i] = u;
                uint4 w;
                w.x = cvt_tf32(rw[i].x); w.y = cvt_tf32(rw[i].y);
                w.z = cvt_tf32(rw[i].z); w.w = cvt_tf32(rw[i].w);
                *(uint4*)&Ws[nxt][rr][kc + 4 * i] = w;
            }
        }
        __syncthreads();
    }

#pragma unroll
    for (int mf = 0; mf < 2; mf++) {
        const int row = bm + wm + mf * 16 + gid;
#pragma unroll
        for (int nb = 0; nb < 8; nb++) {
            const int col = bn + wn + nb * 8 + 2 * tig;
            const float b0 = bias[col], b1 = bias[col + 1];
            *(float2*)(C + (size_t)row * Dm + col) =
                make_float2(acc[mf][nb][0] + b0, acc[mf][nb][1] + b1);
            *(float2*)(C + (size_t)(row + 8) * Dm + col) =
                make_float2(acc[mf][nb][2] + b0, acc[mf][nb][3] + b1);
        }
    }
}

// ---------------------------------------------------------------------------
// tf32 GEMM for Q/O projections (A row-major), as in R3.
// ---------------------------------------------------------------------------
__global__ __launch_bounds__(256)
void gemm_tf32_rm(const float* __restrict__ A, const float* __restrict__ W,
                  const float* __restrict__ bias, float* __restrict__ C)
{
    __shared__ uint32_t As[32][MPAD];
    __shared__ uint32_t Ws[128][WPAD];

    const int bm = blockIdx.x * 128;
    const int bn = blockIdx.y * 128;
    const int tid  = threadIdx.x;
    const int warp = tid >> 5;
    const int lane = tid & 31;
    const int gid  = lane >> 2;
    const int tig  = lane & 3;
    const int wm = (warp >> 1) * 32;
    const int wn = (warp & 1) * 64;

    float acc[2][8][4];
#pragma unroll
    for (int mf = 0; mf < 2; mf++)
#pragma unroll
        for (int nb = 0; nb < 8; nb++)
#pragma unroll
            for (int j = 0; j < 4; j++) acc[mf][nb][j] = 0.f;

    const int rr = tid >> 1;
    const int kc = (tid & 1) * 16;

    for (int k0 = 0; k0 < Dm; k0 += 32) {
        __syncthreads();
#pragma unroll
        for (int i = 0; i < 4; i++) {
            float4 v = *(const float4*)(A + (size_t)(bm + rr) * Dm + k0 + kc + 4 * i);
            As[kc + 4 * i + 0][rr] = cvt_tf32(v.x);
            As[kc + 4 * i + 1][rr] = cvt_tf32(v.y);
            As[kc + 4 * i + 2][rr] = cvt_tf32(v.z);
            As[kc + 4 * i + 3][rr] = cvt_tf32(v.w);
            float4 w = *(const float4*)(W + (size_t)(bn + rr) * Dm + k0 + kc + 4 * i);
            uint4 u;
            u.x = cvt_tf32(w.x); u.y = cvt_tf32(w.y);
            u.z = cvt_tf32(w.z); u.w = cvt_tf32(w.w);
            *(uint4*)&Ws[rr][kc + 4 * i] = u;
        }
        __syncthreads();

#pragma unroll
        for (int kb = 0; kb < 4; kb++) {
            uint32_t a[2][4];
#pragma unroll
            for (int mf = 0; mf < 2; mf++) {
                a[mf][0] = As[kb * 8 + tig    ][wm + mf * 16 + gid    ];
                a[mf][1] = As[kb * 8 + tig    ][wm + mf * 16 + gid + 8];
                a[mf][2] = As[kb * 8 + tig + 4][wm + mf * 16 + gid    ];
                a[mf][3] = As[kb * 8 + tig + 4][wm + mf * 16 + gid + 8];
            }
#pragma unroll
            for (int nb = 0; nb < 8; nb++) {
                uint32_t b0 = Ws[wn + nb * 8 + gid][kb * 8 + tig    ];
                uint32_t b1 = Ws[wn + nb * 8 + gid][kb * 8 + tig + 4];
                mma_tf32(acc[0][nb], a[0], b0, b1);
                mma_tf32(acc[1][nb], a[1], b0, b1);
            }
        }
    }

#pragma unroll
    for (int mf = 0; mf < 2; mf++) {
        const int row = bm + wm + mf * 16 + gid;
#pragma unroll
        for (int nb = 0; nb < 8; nb++) {
            const int col = bn + wn + nb * 8 + 2 * tig;
            const float b0 = bias[col], b1 = bias[col + 1];
            *(float2*)(C + (size_t)row * Dm + col) =
                make_float2(acc[mf][nb][0] + b0, acc[mf][nb][1] + b1);
            *(float2*)(C + (size_t)(row + 8) * Dm + col) =
                make_float2(acc[mf][nb][2] + b0, acc[mf][nb][3] + b1);
        }
    }
}

// ---------------------------------------------------------------------------
// tf32 flash attention, split-KV, double-buffered K/V tiles.
// ---------------------------------------------------------------------------
#define KST 36
#define VST 36

__global__ __launch_bounds__(128)
void attn_mma(const float* __restrict__ Q, const float* __restrict__ K,
              const float* __restrict__ V, float* __restrict__ Po,
              float* __restrict__ Pm, float* __restrict__ Pl)
{
    const int h  = blockIdx.y;
    const int bz = blockIdx.z;
    const int b  = bz >> 1;
    const int sp = bz & 1;
    const int q0 = blockIdx.x * 64;

    __shared__ uint32_t Ks[2][64][KST];
    __shared__ uint32_t Vs[2][64][VST];

    const int tid  = threadIdx.x;
    const int warp = tid >> 5;
    const int lane = tid & 31;
    const int gid  = lane >> 2;
    const int tig  = lane & 3;

    const float scale = 0.17677669529663687f;

    uint32_t qa[4][4];
    {
        const float* Qb = Q + ((size_t)(b * Sq + q0 + warp * 16)) * Dm + h * HD;
#pragma unroll
        for (int kb = 0; kb < 4; kb++) {
            qa[kb][0] = cvt_tf32(Qb[(size_t)gid       * Dm + kb * 8 + tig    ] * scale);
            qa[kb][1] = cvt_tf32(Qb[(size_t)(gid + 8) * Dm + kb * 8 + tig    ] * scale);
            qa[kb][2] = cvt_tf32(Qb[(size_t)gid       * Dm + kb * 8 + tig + 4] * scale);
            qa[kb][3] = cvt_tf32(Qb[(size_t)(gid + 8) * Dm + kb * 8 + tig + 4] * scale);
        }
    }

    float m_lo = -1e30f, m_hi = -1e30f;
    float l_lo = 0.f,    l_hi = 0.f;
    float o[4][4];
#pragma unroll
    for (int nb = 0; nb < 4; nb++)
#pragma unroll
        for (int i = 0; i < 4; i++) o[nb][i] = 0.f;

    const float* Kb = K + (size_t)b * HWk * Dm + h * HD;
    const float* Vb = V + (size_t)b * HWk * Dm + h * HD;

    const int lrow = tid >> 1;
    const int lcol = (tid & 1) * 16;

    const int jbeg = sp * (HWk / NSPLIT);
    const int jend = jbeg + (HWk / NSPLIT);

    float4 rk[4], rv[4];
    // preload first tile
#pragma unroll
    for (int i = 0; i < 4; i++) {
        rk[i] = *(const float4*)(Kb + (size_t)(jbeg + lrow) * Dm + lcol + 4 * i);
        rv[i] = *(const float4*)(Vb + (size_t)(jbeg + lrow) * Dm + lcol + 4 * i);
    }
#pragma unroll
    for (int i = 0; i < 4; i++) {
        uint4 ku, vu;
        ku.x = cvt_tf32(rk[i].x); ku.y = cvt_tf32(rk[i].y);
        ku.z = cvt_tf32(rk[i].z); ku.w = cvt_tf32(rk[i].w);
        vu.x = cvt_tf32(rv[i].x); vu.y = cvt_tf32(rv[i].y);
        vu.z = cvt_tf32(rv[i].z); vu.w = cvt_tf32(rv[i].w);
        *(uint4*)&Ks[0][lrow][lcol + 4 * i] = ku;
        *(uint4*)&Vs[0][lrow][lcol + 4 * i] = vu;
    }
    __syncthreads();

    int stage = 0;
    for (int j0 = jbeg; j0 < jend; j0 += 64) {
        const bool more = (j0 + 64) < jend;
        if (more) {
#pragma unroll
            for (int i = 0; i < 4; i++) {
                rk[i] = *(const float4*)(Kb + (size_t)(j0 + 64 + lrow) * Dm + lcol + 4 * i);
                rv[i] = *(const float4*)(Vb + (size_t)(j0 + 64 + lrow) * Dm + lcol + 4 * i);
            }
        }

        // ---- S = Q K^T ----
        float s[8][4];
#pragma unroll
        for (int nb = 0; nb < 8; nb++)
#pragma unroll
            for (int i = 0; i < 4; i++) s[nb][i] = 0.f;

#pragma unroll
        for (int kb = 0; kb < 4; kb++) {
#pragma unroll
            for (int nb = 0; nb < 8; nb++) {
                uint32_t b0 = Ks[stage][nb * 8 + gid][kb * 8 + tig];
                uint32_t b1 = Ks[stage][nb * 8 + gid][kb * 8 + tig + 4];
                mma_tf32(s[nb], qa[kb], b0, b1);
            }
        }

        // ---- online softmax ----
        float tmax_lo = -1e30f, tmax_hi = -1e30f;
#pragma unroll
        for (int nb = 0; nb < 8; nb++) {
            tmax_lo = fmaxf(tmax_lo, fmaxf(s[nb][0], s[nb][1]));
            tmax_hi = fmaxf(tmax_hi, fmaxf(s[nb][2], s[nb][3]));
        }
        tmax_lo = fmaxf(tmax_lo, __shfl_xor_sync(0xffffffffu, tmax_lo, 1));
        tmax_lo = fmaxf(tmax_lo, __shfl_xor_sync(0xffffffffu, tmax_lo, 2));
        tmax_hi = fmaxf(tmax_hi, __shfl_xor_sync(0xffffffffu, tmax_hi, 1));
        tmax_hi = fmaxf(tmax_hi, __shfl_xor_sync(0xffffffffu, tmax_hi, 2));

        const float mn_lo = fmaxf(m_lo, tmax_lo);
        const float mn_hi = fmaxf(m_hi, tmax_hi);
        const float al_lo = __expf(m_lo - mn_lo);
        const float al_hi = __expf(m_hi - mn_hi);
        m_lo = mn_lo; m_hi = mn_hi;
        l_lo *= al_lo; l_hi *= al_hi;
#pragma unroll
        for (int nb = 0; nb < 4; nb++) {
            o[nb][0] *= al_lo; o[nb][1] *= al_lo;
            o[nb][2] *= al_hi; o[nb][3] *= al_hi;
        }

        // ---- exp + O += P V (c-frag as a-frag, V rows permuted) ----
#pragma unroll
        for (int kb = 0; kb < 8; kb++) {
            const float p0 = __expf(s[kb][0] - mn_lo);
            const float p1 = __expf(s[kb][1] - mn_lo);
            const float p2 = __expf(s[kb][2] - mn_hi);
            const float p3 = __expf(s[kb][3] - mn_hi);
            l_lo += p0 + p1;
            l_hi += p2 + p3;
            uint32_t pa[4];
            pa[0] = cvt_tf32(p0);
            pa[1] = cvt_tf32(p2);
            pa[2] = cvt_tf32(p1);
            pa[3] = cvt_tf32(p3);
#pragma unroll
            for (int nb = 0; nb < 4; nb++) {
                uint32_t b0 = Vs[stage][kb * 8 + 2 * tig    ][nb * 8 + gid];
                uint32_t b1 = Vs[stage][kb * 8 + 2 * tig + 1][nb * 8 + gid];
                mma_tf32(o[nb], pa, b0, b1);
            }
        }

        if (more) {
            const int nxt = stage ^ 1;
#pragma unroll
            for (int i = 0; i < 4; i++) {
                uint4 ku, vu;
                ku.x = cvt_tf32(rk[i].x); ku.y = cvt_tf32(rk[i].y);
                ku.z = cvt_tf32(rk[i].z); ku.w = cvt_tf32(rk[i].w);
                vu.x = cvt_tf32(rv[i].x); vu.y = cvt_tf32(rv[i].y);
                vu.z = cvt_tf32(rv[i].z); vu.w = cvt_tf32(rv[i].w);
                *(uint4*)&Ks[nxt][lrow][lcol + 4 * i] = ku;
                *(uint4*)&Vs[nxt][lrow][lcol + 4 * i] = vu;
            }
        }
        __syncthreads();
        stage ^= 1;
    }

    l_lo += __shfl_xor_sync(0xffffffffu, l_lo, 1);
    l_lo += __shfl_xor_sync(0xffffffffu, l_lo, 2);
    l_hi += __shfl_xor_sync(0xffffffffu, l_hi, 1);
    l_hi += __shfl_xor_sync(0xffffffffu, l_hi, 2);

    const int row0 = (((b * NH + h) * NSPLIT) + sp) * Sq + q0 + warp * 16;
#pragma unroll
    for (int nb = 0; nb < 4; nb++) {
        *(float2*)(Po + (size_t)(row0 + gid)     * HD + nb * 8 + 2 * tig) =
            make_float2(o[nb][0], o[nb][1]);
        *(float2*)(Po + (size_t)(row0 + gid + 8) * HD + nb * 8 + 2 * tig) =
            make_float2(o[nb][2], o[nb][3]);
    }
    if (tig == 0) {
        Pm[row0 + gid]     = m_lo;  Pl[row0 + gid]     = l_lo;
        Pm[row0 + gid + 8] = m_hi;  Pl[row0 + gid + 8] = l_hi;
    }
}

// ---------------------------------------------------------------------------
// combine split partials -> (B,S,D)
// ---------------------------------------------------------------------------
__global__ __launch_bounds__(256)
void attn_combine(const float* __restrict__ Po, const float* __restrict__ Pm,
                  const float* __restrict__ Pl, float* __restrict__ Aout)
{
    const int t = blockIdx.x * 256 + threadIdx.x;
    const int row = t >> 2;
    const int dc  = (t & 3) * 8;
    const int bh  = row / Sq;
    const int q   = row % Sq;
    const int b   = bh / NH;
    const int h   = bh % NH;

    const size_t i0 = (size_t)(bh * NSPLIT + 0) * Sq + q;
    const size_t i1 = (size_t)(bh * NSPLIT + 1) * Sq + q;
    const float m0 = Pm[i0], m1 = Pm[i1];
    const float l0 = Pl[i0], l1 = Pl[i1];
    const float m  = fmaxf(m0, m1);
    const float w0 = __expf(m0 - m);
    const float w1 = __expf(m1 - m);
    const float inv = 1.f / (l0 * w0 + l1 * w1);

    const float* o0 = Po + i0 * HD + dc;
    const float* o1 = Po + i1 * HD + dc;
    float* out = Aout + ((size_t)(b * Sq + q)) * Dm + h * HD + dc;
#pragma unroll
    for (int i = 0; i < 8; i += 4) {
        float4 a = *(const float4*)(o0 + i);
        float4 c = *(const float4*)(o1 + i);
        float4 r;
        r.x = (a.x * w0 + c.x * w1) * inv;
        r.y = (a.y * w0 + c.y * w1) * inv;
        r.z = (a.z * w0 + c.z * w1) * inv;
        r.w = (a.w * w0 + c.w * w1) * inv;
        *(float4*)(out + i) = r;
    }
}

// ---------------------------------------------------------------------------
// Launch
// ---------------------------------------------------------------------------
extern "C" void kernel_launch(void* const* d_in, const int* in_sizes, int n_in,
                              void* d_out, int out_size)
{
    const float* query = (const float*)d_in[0];
    const float* keyv  = (const float*)d_in[1];
    const float* Wq    = (const float*)d_in[2];
    const float* bq    = (const float*)d_in[3];
    const float* Wk    = (const float*)d_in[4];
    const float* bk    = (const float*)d_in[5];
    const float* Wv    = (const float*)d_in[6];
    const float* bv    = (const float*)d_in[7];
    const float* Wo    = (const float*)d_in[8];
    const float* bo    = (const float*)d_in[9];
    float* out = (float*)d_out;

    float *dQ, *dK, *dV, *dA, *dPo, *dPm, *dPl;
    cudaGetSymbolAddress((void**)&dQ, g_Q);
    cudaGetSymbolAddress((void**)&dK, g_K);
    cudaGetSymbolAddress((void**)&dV, g_V);
    cudaGetSymbolAddress((void**)&dA, g_A);
    cudaGetSymbolAddress((void**)&dPo, g_Po);
    cudaGetSymbolAddress((void**)&dPm, g_Pm);
    cudaGetSymbolAddress((void**)&dPl, g_Pl);

    // Q projection
    {
        dim3 grid((Bsz * Sq) / 128, Dm / 128);
        gemm_tf32_rm<<<grid, 256>>>(query, Wq, bq, dQ);
    }
    // fused K+V projections, all batches, ONE launch
    {
        dim3 grid(HWk / 128, Dm / 128, Bsz * 2);
        gemm_kv_fused<<<grid, 256>>>(keyv, Wk, bk, Wv, bv, dK, dV);
    }
    // attention (split-KV)
    {
        dim3 grid(Sq / 64, NH, Bsz * NSPLIT);
        attn_mma<<<grid, 128>>>(dQ, dK, dV, dPo, dPm, dPl);
    }
    // combine
    {
        attn_combine<<<(Bsz * NH * Sq * 4) / 256, 256>>>(dPo, dPm, dPl, dA);
    }
    // output projection -> d_out
    {
        dim3 grid((Bsz * Sq) / 128, Dm / 128);
        gemm_tf32_rm<<<grid, 256>>>(dA, Wo, bo, out);
    }
}